// round 4
// baseline (speedup 1.0000x reference)
#include <cuda_runtime.h>
#include <cstdint>

#define NB 64
#define NL 64
#define NC 16
#define DM 450          // EMB(300) + 3*50
#define NTOK 8192       // 2 * B * L

typedef unsigned long long ull;

__device__ __forceinline__ void upk2(ull v, float& lo, float& hi) {
    asm("mov.b64 {%0, %1}, %2;" : "=f"(lo), "=f"(hi) : "l"(v));
}
__device__ __forceinline__ void fma2(ull& d, ull a, ull b) {
    asm("fma.rn.f32x2 %0, %1, %2, %0;" : "+l"(d) : "l"(a), "l"(b));
}

__device__ float g_x[(size_t)NTOK * DM];
__device__ float g_y[(size_t)NTOK * DM];
__device__ float g_M[60000];

// ---------------------------------------------------------------------------
// 1) Precompute char tables: M[k][v][f] = sum_ch cemb[v][ch] * w[f][ch][k]
// ---------------------------------------------------------------------------
__global__ void precomp_kernel(const float* __restrict__ cemb,
                               const float* __restrict__ w3,
                               const float* __restrict__ w4,
                               const float* __restrict__ w5) {
    int idx = blockIdx.x * blockDim.x + threadIdx.x;
    if (idx >= 60000) return;
    const float* W;
    int WD, local;
    if (idx < 15000)      { W = w3; WD = 3; local = idx; }
    else if (idx < 35000) { W = w4; WD = 4; local = idx - 15000; }
    else                  { W = w5; WD = 5; local = idx - 35000; }
    int f  = local % 50;
    int kv = local / 50;
    int v  = kv % 100;
    int k  = kv / 100;
    const float* e  = cemb + v * 64;
    const float* wp = W + (size_t)f * 64 * WD + k;
    float s = 0.f;
#pragma unroll 8
    for (int ch = 0; ch < 64; ch++) s += e[ch] * wp[ch * WD];
    g_M[idx] = s;
}

// ---------------------------------------------------------------------------
// 2) Embedding + char features -> g_x[tok][450]
// ---------------------------------------------------------------------------
__global__ void embed_kernel(const int* __restrict__ q1, const int* __restrict__ q2,
                             const int* __restrict__ q1c, const int* __restrict__ q2c,
                             const float* __restrict__ wemb,
                             const float* __restrict__ b3, const float* __restrict__ b4,
                             const float* __restrict__ b5) {
    int tok = blockIdx.x;
    int r   = tok >> 12;
    int li  = tok & 4095;
    const int* q  = r ? q2 : q1;
    const int* qc = r ? q2c : q1c;
    int tid = threadIdx.x;

    __shared__ int ids[16];
    if (tid < 16) ids[tid] = qc[li * 16 + tid];
    __syncthreads();

    float* xrow = g_x + (size_t)tok * DM;
    const float* we = wemb + (size_t)q[li] * 300;
    for (int i = tid; i < 300; i += blockDim.x) xrow[i] = we[i];

    int f = tid;
    if (f < 150) {
        int fi, base, wd;
        float bias;
        if (f < 50)       { wd = 3; fi = f;       base = 0;     bias = b3[fi]; }
        else if (f < 100) { wd = 4; fi = f - 50;  base = 15000; bias = b4[fi]; }
        else              { wd = 5; fi = f - 100; base = 35000; bias = b5[fi]; }
        float m = 0.f;
        int tout = 16 - wd + 1;
        for (int t = 0; t < tout; t++) {
            float h = bias;
            for (int k = 0; k < wd; k++)
                h += g_M[base + (k * 100 + ids[t + k]) * 50 + fi];
            m = fmaxf(m, h);
        }
        xrow[300 + f] = m;
    }
}

// ---------------------------------------------------------------------------
// 3) Highway: y = x @ W^T + b ; out = sig(y)*relu(y) + (1-sig(y))*x
//    Zero-MOV f32x2: A row-pairs + B dup-pairs straight from LDS.128.
// ---------------------------------------------------------------------------
#define HBM 128
#define HBN 64
#define HBK 32

__global__ __launch_bounds__(256, 4) void highway_kernel(int dir,
        const float* __restrict__ W, const float* __restrict__ bias) {
    const float* X = dir ? g_y : g_x;
    float* OUT     = dir ? g_x : g_y;
    __shared__ float As[HBK][HBM + 4];          // [k][m]
    __shared__ float Bs2[HBK][2 * HBN + 8];     // [k][2n] duplicated pairs
    int bm = blockIdx.y * HBM;
    int bn = blockIdx.x * HBN;
    int tid = threadIdx.x;
    int tm = (tid >> 4) * 8;
    int tn = (tid & 15) * 4;
    // acc[p][j]: rows (tm+2p, tm+2p+1) packed, col tn+j
    ull acc[4][4] = {};

    for (int k0 = 0; k0 < DM; k0 += HBK) {
        // A tile: 128 rows x 32 k via float2 (DM even => 8B aligned)
        for (int idx = tid; idx < HBM * 16; idx += 256) {
            int m = idx >> 4, kp = idx & 15;
            int kk = k0 + 2 * kp;
            float2 v = make_float2(0.f, 0.f);
            if (kk < DM) v = *(const float2*)&X[(size_t)(bm + m) * DM + kk];
            As[2 * kp][m]     = v.x;
            As[2 * kp + 1][m] = v.y;
        }
        // B tile (duplicated): 64 n x 32 k
        for (int idx = tid; idx < HBN * 16; idx += 256) {
            int n = idx >> 4, kp = idx & 15;
            int kk = k0 + 2 * kp;
            int gn = bn + n;
            float2 v = make_float2(0.f, 0.f);
            if (gn < DM && kk < DM) v = *(const float2*)&W[(size_t)gn * DM + kk];
            Bs2[2 * kp][2 * n]         = v.x;
            Bs2[2 * kp][2 * n + 1]     = v.x;
            Bs2[2 * kp + 1][2 * n]     = v.y;
            Bs2[2 * kp + 1][2 * n + 1] = v.y;
        }
        __syncthreads();
#pragma unroll 8
        for (int k = 0; k < HBK; k++) {
            ulonglong2 a0 = *(const ulonglong2*)&As[k][tm];
            ulonglong2 a1 = *(const ulonglong2*)&As[k][tm + 4];
            ulonglong2 b0 = *(const ulonglong2*)&Bs2[k][2 * tn];
            ulonglong2 b1 = *(const ulonglong2*)&Bs2[k][2 * tn + 4];
            fma2(acc[0][0], a0.x, b0.x); fma2(acc[1][0], a0.y, b0.x);
            fma2(acc[2][0], a1.x, b0.x); fma2(acc[3][0], a1.y, b0.x);
            fma2(acc[0][1], a0.x, b0.y); fma2(acc[1][1], a0.y, b0.y);
            fma2(acc[2][1], a1.x, b0.y); fma2(acc[3][1], a1.y, b0.y);
            fma2(acc[0][2], a0.x, b1.x); fma2(acc[1][2], a0.y, b1.x);
            fma2(acc[2][2], a1.x, b1.x); fma2(acc[3][2], a1.y, b1.x);
            fma2(acc[0][3], a0.x, b1.y); fma2(acc[1][3], a0.y, b1.y);
            fma2(acc[2][3], a1.x, b1.y); fma2(acc[3][3], a1.y, b1.y);
        }
        __syncthreads();
    }

#pragma unroll
    for (int p = 0; p < 4; p++) {
        int m0 = bm + tm + 2 * p;
#pragma unroll
        for (int j = 0; j < 4; j++) {
            int n = bn + tn + j;
            if (n < DM) {
                float y0, y1;
                upk2(acc[p][j], y0, y1);
                float yy = y0 + bias[n];
                float g  = 1.f / (1.f + __expf(-yy));
                float xv = X[(size_t)m0 * DM + n];
                OUT[(size_t)m0 * DM + n] = g * fmaxf(yy, 0.f) + (1.f - g) * xv;
                yy = y1 + bias[n];
                g  = 1.f / (1.f + __expf(-yy));
                xv = X[(size_t)(m0 + 1) * DM + n];
                OUT[(size_t)(m0 + 1) * DM + n] = g * fmaxf(yy, 0.f) + (1.f - g) * xv;
            }
        }
    }
}

// ---------------------------------------------------------------------------
// 4) Self-attention, split: grid (4, 128): block = (batch, 16-row group).
//    PING-PONG (no in-place): iter0 Xin=g_x -> Xout=g_y (att+x);
//    iter1 Xin=g_y -> dout (att only). Avoids cross-block races.
//    256 threads = 8 warps; warp w owns local rows 2w, 2w+1.
//    scores[i][j] = s1[i] + s2[j] + sum_d x[i,d]*w3[d]*x[j,d] + b
//    soft mask: logits = (j<len) ? score : -1e-9, all cols in softmax.
// ---------------------------------------------------------------------------
__global__ __launch_bounds__(256) void attn_kernel(
        const int* __restrict__ q1_len, const int* __restrict__ q2_len,
        const float* __restrict__ attw, const float* __restrict__ attb,
        int it, int residual,
        const float* __restrict__ Xin_base, float* __restrict__ Xout_base) {
    int batch = blockIdx.y;
    int row0  = blockIdx.x * 16;
    int r = batch >> 6, b = batch & 63;
    int len = (r ? q2_len : q1_len)[b];
    const float* aw = attw + it * (3 * DM);
    float ab = attb[it];
    const float* X = Xin_base + (size_t)batch * 64 * DM;
    float* OUT     = Xout_base + (size_t)batch * 64 * DM;

    __shared__ float xw[64][68];    // A: [d][j]=x[j]*w3 ; C: reused [j][d] raw x
    __shared__ float xsD[64][36];   // A: [d][2r] own-row dup
    __shared__ float pT2[64][36];   // B->C: [j][2r] prob dup
    __shared__ float s1s[16], s2s[64];

    int tid  = threadIdx.x;
    int warp = tid >> 5, lane = tid & 31;
    int tj2  = lane * 2;

    // ---- s1/s2 pre-pass: 80 full-DM dots from global ----
    for (int dot = warp; dot < 80; dot += 8) {
        const float* wv;
        const float* xv;
        if (dot < 64) { wv = aw + DM;  xv = X + dot * DM; }               // s2[col]
        else          { wv = aw;       xv = X + (row0 + dot - 64) * DM; } // s1[row]
        float a = 0.f;
        for (int d = lane; d < DM; d += 32) a += xv[d] * wv[d];
#pragma unroll
        for (int off = 16; off > 0; off >>= 1)
            a += __shfl_down_sync(0xffffffffu, a, off);
        if (lane == 0) {
            if (dot < 64) s2s[dot] = a;
            else          s1s[dot - 64] = a + ab;
        }
    }

    ull acc0 = 0, acc1 = 0;    // rows 2w, 2w+1 ; cols (tj2, tj2+1)

    // ---- Phase A: score GEMM over d-tiles ----
    for (int d0 = 0; d0 < DM; d0 += 64) {
        int dn = DM - d0; if (dn > 64) dn = 64;
        __syncthreads();
        for (int idx = tid; idx < 64 * 64; idx += 256) {
            int j = idx >> 6, d = idx & 63;
            float v = 0.f;
            if (d < dn) v = X[j * DM + d0 + d] * aw[2 * DM + d0 + d];
            xw[d][j] = v;
        }
        for (int idx = tid; idx < 16 * 64; idx += 256) {
            int rr = idx >> 6, d = idx & 63;
            float v = (d < dn) ? X[(row0 + rr) * DM + d0 + d] : 0.f;
            xsD[d][2 * rr]     = v;
            xsD[d][2 * rr + 1] = v;
        }
        __syncthreads();
#pragma unroll 4
        for (int d = 0; d < 64; d++) {
            ulonglong2 a2 = *(const ulonglong2*)&xsD[d][4 * warp];
            ull bw = *(const ull*)&xw[d][tj2];
            fma2(acc0, a2.x, bw);
            fma2(acc1, a2.y, bw);
        }
    }

    // ---- Phase B: softmax in-warp (warp owns 2 full rows) ----
    {
        float2 s2p = *(const float2*)&s2s[tj2];
#pragma unroll
        for (int i = 0; i < 2; i++) {
            int row = 2 * warp + i;
            float base = s1s[row];
            float v0, v1;
            upk2(i ? acc1 : acc0, v0, v1);
            v0 += base + s2p.x;
            v1 += base + s2p.y;
            float l0 = (tj2     < len) ? v0 : -1e-9f;
            float l1 = (tj2 + 1 < len) ? v1 : -1e-9f;
            float mx = fmaxf(l0, l1);
#pragma unroll
            for (int off = 16; off > 0; off >>= 1)
                mx = fmaxf(mx, __shfl_xor_sync(0xffffffffu, mx, off));
            float e0 = __expf(l0 - mx), e1 = __expf(l1 - mx);
            float s = e0 + e1;
#pragma unroll
            for (int off = 16; off > 0; off >>= 1)
                s += __shfl_xor_sync(0xffffffffu, s, off);
            float inv = 1.f / s;
            float p0 = e0 * inv, p1 = e1 * inv;
            pT2[tj2][2 * row]         = p0;
            pT2[tj2][2 * row + 1]     = p0;
            pT2[tj2 + 1][2 * row]     = p1;
            pT2[tj2 + 1][2 * row + 1] = p1;
        }
    }

    // ---- Phase C: att = P @ x ; write out (att+x or att) ----
    float* xs = &xw[0][0];   // reuse as [j][68] row-major
    for (int d0 = 0; d0 < DM; d0 += 64) {
        int dn = DM - d0; if (dn > 64) dn = 64;
        __syncthreads();     // covers pT2 writes / previous xw reads
        for (int idx = tid; idx < 64 * 32; idx += 256) {
            int j = idx >> 5, dp = idx & 31;
            float2 v = make_float2(0.f, 0.f);
            if (2 * dp < dn) v = *(const float2*)&X[j * DM + d0 + 2 * dp];
            *(float2*)&xs[j * 68 + 2 * dp] = v;
        }
        __syncthreads();
        ull o0 = 0, o1 = 0;   // rows 2w, 2w+1 ; d-cols (tj2, tj2+1)
#pragma unroll 4
        for (int j = 0; j < 64; j++) {
            ulonglong2 p2 = *(const ulonglong2*)&pT2[j][4 * warp];
            ull xv = *(const ull*)&xs[j * 68 + tj2];
            fma2(o0, p2.x, xv);
            fma2(o1, p2.y, xv);
        }
        int d = d0 + tj2;
#pragma unroll
        for (int i = 0; i < 2; i++) {
            int grow = row0 + 2 * warp + i;
            float a0, a1;
            upk2(i ? o1 : o0, a0, a1);
            if (residual) {
                float2 xv = *(const float2*)&xs[grow * 68 + tj2];
                a0 += xv.x;
                a1 += xv.y;
            }
            if (d < DM)     OUT[grow * DM + d]     = a0;
            if (d + 1 < DM) OUT[grow * DM + d + 1] = a1;
        }
    }
}

// ---------------------------------------------------------------------------
extern "C" void kernel_launch(void* const* d_in, const int* in_sizes, int n_in,
                              void* d_out, int out_size) {
    const int*   q1     = (const int*)d_in[0];
    const int*   q2     = (const int*)d_in[1];
    const int*   q1_len = (const int*)d_in[2];
    const int*   q2_len = (const int*)d_in[3];
    const int*   q1c    = (const int*)d_in[4];
    const int*   q2c    = (const int*)d_in[5];
    const float* wemb   = (const float*)d_in[6];
    const float* cemb   = (const float*)d_in[7];
    const float* cw3    = (const float*)d_in[8];
    const float* cb3    = (const float*)d_in[9];
    const float* cw4    = (const float*)d_in[10];
    const float* cb4    = (const float*)d_in[11];
    const float* cw5    = (const float*)d_in[12];
    const float* cb5    = (const float*)d_in[13];
    const float* hw_w   = (const float*)d_in[14];
    const float* hw_b   = (const float*)d_in[15];
    const float* attw   = (const float*)d_in[16];
    const float* attb   = (const float*)d_in[17];
    float* out = (float*)d_out;

    float* gx;
    float* gy;
    cudaGetSymbolAddress((void**)&gx, g_x);
    cudaGetSymbolAddress((void**)&gy, g_y);

    precomp_kernel<<<(60000 + 255) / 256, 256>>>(cemb, cw3, cw4, cw5);
    embed_kernel<<<NTOK, 160>>>(q1, q2, q1c, q2c, wemb, cb3, cb4, cb5);
    highway_kernel<<<dim3(8, 64), 256>>>(0, hw_w, hw_b);   // g_x -> g_y
    highway_kernel<<<dim3(8, 64), 256>>>(1, hw_w, hw_b);   // g_y -> g_x
    // attn iter0: g_x -> g_y (att + x) ; iter1: g_y -> out (att)
    attn_kernel<<<dim3(4, 128), 256>>>(q1_len, q2_len, attw, attb, 0, 1, gx, gy);
    attn_kernel<<<dim3(4, 128), 256>>>(q1_len, q2_len, attw, attb, 1, 0, gy, out);
}

// round 5
// speedup vs baseline: 1.3159x; 1.3159x over previous
#include <cuda_runtime.h>
#include <cstdint>

#define NB 64
#define NL 64
#define NC 16
#define DM 450          // EMB(300) + 3*50
#define NTOK 8192       // 2 * B * L

typedef unsigned long long ull;

__device__ __forceinline__ void upk2(ull v, float& lo, float& hi) {
    asm("mov.b64 {%0, %1}, %2;" : "=f"(lo), "=f"(hi) : "l"(v));
}
__device__ __forceinline__ void fma2(ull& d, ull a, ull b) {
    asm("fma.rn.f32x2 %0, %1, %2, %0;" : "+l"(d) : "l"(a), "l"(b));
}

__device__ float g_x[(size_t)NTOK * DM];
__device__ float g_y[(size_t)NTOK * DM];
__device__ float g_M[60000];
__device__ float g_s1[NTOK];
__device__ float g_s2[NTOK];

// ---------------------------------------------------------------------------
// 1) Precompute char tables: M[k][v][f] = sum_ch cemb[v][ch] * w[f][ch][k]
// ---------------------------------------------------------------------------
__global__ void precomp_kernel(const float* __restrict__ cemb,
                               const float* __restrict__ w3,
                               const float* __restrict__ w4,
                               const float* __restrict__ w5) {
    int idx = blockIdx.x * blockDim.x + threadIdx.x;
    if (idx >= 60000) return;
    const float* W;
    int WD, local;
    if (idx < 15000)      { W = w3; WD = 3; local = idx; }
    else if (idx < 35000) { W = w4; WD = 4; local = idx - 15000; }
    else                  { W = w5; WD = 5; local = idx - 35000; }
    int f  = local % 50;
    int kv = local / 50;
    int v  = kv % 100;
    int k  = kv / 100;
    const float* e  = cemb + v * 64;
    const float* wp = W + (size_t)f * 64 * WD + k;
    float s = 0.f;
#pragma unroll 8
    for (int ch = 0; ch < 64; ch++) s += e[ch] * wp[ch * WD];
    g_M[idx] = s;
}

// ---------------------------------------------------------------------------
// 2) Embedding + char features -> g_x[tok][450]
// ---------------------------------------------------------------------------
__global__ void embed_kernel(const int* __restrict__ q1, const int* __restrict__ q2,
                             const int* __restrict__ q1c, const int* __restrict__ q2c,
                             const float* __restrict__ wemb,
                             const float* __restrict__ b3, const float* __restrict__ b4,
                             const float* __restrict__ b5) {
    int tok = blockIdx.x;
    int r   = tok >> 12;
    int li  = tok & 4095;
    const int* q  = r ? q2 : q1;
    const int* qc = r ? q2c : q1c;
    int tid = threadIdx.x;

    __shared__ int ids[16];
    if (tid < 16) ids[tid] = qc[li * 16 + tid];
    __syncthreads();

    float* xrow = g_x + (size_t)tok * DM;
    const float* we = wemb + (size_t)q[li] * 300;
    for (int i = tid; i < 300; i += blockDim.x) xrow[i] = we[i];

    int f = tid;
    if (f < 150) {
        int fi, base, wd;
        float bias;
        if (f < 50)       { wd = 3; fi = f;       base = 0;     bias = b3[fi]; }
        else if (f < 100) { wd = 4; fi = f - 50;  base = 15000; bias = b4[fi]; }
        else              { wd = 5; fi = f - 100; base = 35000; bias = b5[fi]; }
        float m = 0.f;
        int tout = 16 - wd + 1;
        for (int t = 0; t < tout; t++) {
            float h = bias;
            for (int k = 0; k < wd; k++)
                h += g_M[base + (k * 100 + ids[t + k]) * 50 + fi];
            m = fmaxf(m, h);
        }
        xrow[300 + f] = m;
    }
}

// ---------------------------------------------------------------------------
// 3) Highway: y = x @ W^T + b ; out = sig(y)*relu(y) + (1-sig(y))*x
//    N-pair packed f32x2: B read as natural conflict-free pairs,
//    A duplicated in smem (warp-broadcast => dup is free on crossbar).
// ---------------------------------------------------------------------------
#define HBM 128
#define HBN 64
#define HBK 32
#define ASW 268   // padded row width for AsD (2*128 + 12): 16B-aligned, low store conflicts

__global__ __launch_bounds__(256, 4) void highway_kernel(int dir,
        const float* __restrict__ W, const float* __restrict__ bias) {
    const float* X = dir ? g_y : g_x;
    float* OUT     = dir ? g_x : g_y;
    __shared__ float AsD[HBK][ASW];         // [k][2m] duplicated row pairs
    __shared__ float Bs[HBK][HBN + 4];      // [k][n] natural
    int bm = blockIdx.y * HBM;
    int bn = blockIdx.x * HBN;
    int tid = threadIdx.x;
    int tm = (tid >> 4) * 8;
    int tn = (tid & 15) * 4;
    // acc[i][p]: row tm+i, col pair (tn+2p, tn+2p+1)
    ull acc[8][2] = {};

    for (int k0 = 0; k0 < DM; k0 += HBK) {
        // A tile: 128 rows x 32 k via float2, stored duplicated
        for (int idx = tid; idx < HBM * 16; idx += 256) {
            int m = idx >> 4, kp = idx & 15;
            int kk = k0 + 2 * kp;
            float2 v = make_float2(0.f, 0.f);
            if (kk < DM) v = *(const float2*)&X[(size_t)(bm + m) * DM + kk];
            *(float2*)&AsD[2 * kp][2 * m]     = make_float2(v.x, v.x);
            *(float2*)&AsD[2 * kp + 1][2 * m] = make_float2(v.y, v.y);
        }
        // B tile: 64 n x 32 k, natural layout
        for (int idx = tid; idx < HBN * 16; idx += 256) {
            int n = idx >> 4, kp = idx & 15;
            int kk = k0 + 2 * kp;
            int gn = bn + n;
            float2 v = make_float2(0.f, 0.f);
            if (gn < DM && kk < DM) v = *(const float2*)&W[(size_t)gn * DM + kk];
            Bs[2 * kp][n]     = v.x;
            Bs[2 * kp + 1][n] = v.y;
        }
        __syncthreads();
#pragma unroll 8
        for (int k = 0; k < HBK; k++) {
            ulonglong2 b = *(const ulonglong2*)&Bs[k][tn];       // (b0,b1),(b2,b3)
            ulonglong2 a;
            a = *(const ulonglong2*)&AsD[k][2 * tm];             // (r0,r0),(r1,r1)
            fma2(acc[0][0], a.x, b.x); fma2(acc[0][1], a.x, b.y);
            fma2(acc[1][0], a.y, b.x); fma2(acc[1][1], a.y, b.y);
            a = *(const ulonglong2*)&AsD[k][2 * tm + 4];
            fma2(acc[2][0], a.x, b.x); fma2(acc[2][1], a.x, b.y);
            fma2(acc[3][0], a.y, b.x); fma2(acc[3][1], a.y, b.y);
            a = *(const ulonglong2*)&AsD[k][2 * tm + 8];
            fma2(acc[4][0], a.x, b.x); fma2(acc[4][1], a.x, b.y);
            fma2(acc[5][0], a.y, b.x); fma2(acc[5][1], a.y, b.y);
            a = *(const ulonglong2*)&AsD[k][2 * tm + 12];
            fma2(acc[6][0], a.x, b.x); fma2(acc[6][1], a.x, b.y);
            fma2(acc[7][0], a.y, b.x); fma2(acc[7][1], a.y, b.y);
        }
        __syncthreads();
    }

#pragma unroll
    for (int i = 0; i < 8; i++) {
        int m = bm + tm + i;
#pragma unroll
        for (int p = 0; p < 2; p++) {
            int n0 = bn + tn + 2 * p;
            if (n0 < DM) {   // n0 even, DM even => n0+1 < DM too
                float y0, y1;
                upk2(acc[i][p], y0, y1);
                float2 bb = *(const float2*)&bias[n0];
                float2 xv = *(const float2*)&X[(size_t)m * DM + n0];
                float yy0 = y0 + bb.x;
                float g0  = 1.f / (1.f + __expf(-yy0));
                float yy1 = y1 + bb.y;
                float g1  = 1.f / (1.f + __expf(-yy1));
                float2 o;
                o.x = g0 * fmaxf(yy0, 0.f) + (1.f - g0) * xv.x;
                o.y = g1 * fmaxf(yy1, 0.f) + (1.f - g1) * xv.y;
                *(float2*)&OUT[(size_t)m * DM + n0] = o;
            }
        }
    }
}

// ---------------------------------------------------------------------------
// 4a) s1/s2 dots for one attn iteration: s1 = x.w1, s2 = x.w2, all 64 rows.
//     grid 128 (batch), 256 threads.
// ---------------------------------------------------------------------------
__global__ __launch_bounds__(256) void sdots_kernel(
        const float* __restrict__ Xin_base, const float* __restrict__ attw, int it) {
    int batch = blockIdx.x;
    const float* X  = Xin_base + (size_t)batch * 64 * DM;
    const float* aw = attw + it * (3 * DM);
    int tid = threadIdx.x;
    int warp = tid >> 5, lane = tid & 31;

    for (int dot = warp; dot < 128; dot += 8) {
        int row = dot & 63;
        const float* wv = (dot < 64) ? (aw + DM) : aw;   // <64: s2(w2), else s1(w1)
        const float* xv = X + row * DM;
        float a = 0.f;
        for (int d = lane * 2; d < DM; d += 64) {
            float2 x2 = *(const float2*)&xv[d];
            float2 w2 = *(const float2*)&wv[d];
            a += x2.x * w2.x + x2.y * w2.y;
        }
#pragma unroll
        for (int off = 16; off > 0; off >>= 1)
            a += __shfl_down_sync(0xffffffffu, a, off);
        if (lane == 0) {
            if (dot < 64) g_s2[batch * 64 + row] = a;
            else          g_s1[batch * 64 + row] = a;
        }
    }
}

// ---------------------------------------------------------------------------
// 4b) Self-attention: grid (2, 128), block = (batch, 32-row group), 256 thr.
//     Warp w owns local rows 4w..4w+3; lane owns col pair (2l, 2l+1).
//    scores[i][j] = s1[i] + s2[j] + sum_d x[i,d]*w3[d]*x[j,d] + b
//    soft mask: logits = (j<len) ? score : -1e-9, all cols in softmax.
//    Ping-pong: iter0 g_x -> g_y (att+x), iter1 g_y -> dout (att).
// ---------------------------------------------------------------------------
__global__ __launch_bounds__(256) void attn_kernel(
        const int* __restrict__ q1_len, const int* __restrict__ q2_len,
        const float* __restrict__ attw, const float* __restrict__ attb,
        int it, int residual,
        const float* __restrict__ Xin_base, float* __restrict__ Xout_base) {
    int batch = blockIdx.y;
    int row0  = blockIdx.x * 32;
    int r = batch >> 6, b = batch & 63;
    int len = (r ? q2_len : q1_len)[b];
    const float* aw = attw + it * (3 * DM);
    float ab = attb[it];
    const float* X = Xin_base + (size_t)batch * 64 * DM;
    float* OUT     = Xout_base + (size_t)batch * 64 * DM;

    __shared__ float xw[64][68];    // A: [d][j]=x[j]*w3 ; C: reused [j][d] raw x
    __shared__ float xsD[64][68];   // A: [d][2r] own-row dup ; B/C: pT2[j][2r] probs dup
    __shared__ float s1s[32], s2s[64];

    int tid  = threadIdx.x;
    int warp = tid >> 5, lane = tid & 31;
    int tj2  = lane * 2;

    if (tid < 64)      s2s[tid] = g_s2[batch * 64 + tid];
    else if (tid < 96) s1s[tid - 64] = g_s1[batch * 64 + row0 + (tid - 64)] + ab;

    ull acc[4] = {0, 0, 0, 0};   // rows 4w+i, cols (tj2, tj2+1)

    // ---- Phase A: score GEMM over d-tiles ----
    for (int d0 = 0; d0 < DM; d0 += 64) {
        int dn = DM - d0; if (dn > 64) dn = 64;
        __syncthreads();
        for (int idx = tid; idx < 64 * 64; idx += 256) {
            int j = idx >> 6, d = idx & 63;
            float v = 0.f;
            if (d < dn) v = X[j * DM + d0 + d] * aw[2 * DM + d0 + d];
            xw[d][j] = v;
        }
        for (int idx = tid; idx < 32 * 64; idx += 256) {
            int rr = idx >> 6, d = idx & 63;
            float v = (d < dn) ? X[(row0 + rr) * DM + d0 + d] : 0.f;
            *(float2*)&xsD[d][2 * rr] = make_float2(v, v);
        }
        __syncthreads();
#pragma unroll 4
        for (int d = 0; d < 64; d++) {
            ulonglong2 aA = *(const ulonglong2*)&xsD[d][8 * warp];      // rows 4w,4w+1
            ulonglong2 aB = *(const ulonglong2*)&xsD[d][8 * warp + 4];  // rows 4w+2,4w+3
            ull bw = *(const ull*)&xw[d][tj2];
            fma2(acc[0], aA.x, bw);
            fma2(acc[1], aA.y, bw);
            fma2(acc[2], aB.x, bw);
            fma2(acc[3], aB.y, bw);
        }
    }
    __syncthreads();   // xsD phase-A reads done before pT2 overwrites it

    // ---- Phase B: softmax in-warp; write probs dup-transposed into xsD ----
    {
        float2 s2p = *(const float2*)&s2s[tj2];
#pragma unroll
        for (int i = 0; i < 4; i++) {
            int lr = 4 * warp + i;
            float base = s1s[lr];
            float v0, v1;
            upk2(acc[i], v0, v1);
            v0 += base + s2p.x;
            v1 += base + s2p.y;
            float l0 = (tj2     < len) ? v0 : -1e-9f;
            float l1 = (tj2 + 1 < len) ? v1 : -1e-9f;
            float mx = fmaxf(l0, l1);
#pragma unroll
            for (int off = 16; off > 0; off >>= 1)
                mx = fmaxf(mx, __shfl_xor_sync(0xffffffffu, mx, off));
            float e0 = __expf(l0 - mx), e1 = __expf(l1 - mx);
            float s = e0 + e1;
#pragma unroll
            for (int off = 16; off > 0; off >>= 1)
                s += __shfl_xor_sync(0xffffffffu, s, off);
            float inv = 1.f / s;
            *(float2*)&xsD[tj2][2 * lr]     = make_float2(e0 * inv, e0 * inv);
            *(float2*)&xsD[tj2 + 1][2 * lr] = make_float2(e1 * inv, e1 * inv);
        }
    }

    // ---- Phase C: att = P @ x ; write out (att+x or att) ----
    float* xs = &xw[0][0];   // reuse as [j][68] row-major (all 64 rows)
    for (int d0 = 0; d0 < DM; d0 += 64) {
        int dn = DM - d0; if (dn > 64) dn = 64;
        __syncthreads();     // covers pT2(xsD) writes & prior xs reads
        for (int idx = tid; idx < 64 * 32; idx += 256) {
            int j = idx >> 5, dp = idx & 31;
            float2 v = make_float2(0.f, 0.f);
            if (2 * dp < dn) v = *(const float2*)&X[j * DM + d0 + 2 * dp];
            *(float2*)&xs[j * 68 + 2 * dp] = v;
        }
        __syncthreads();
        ull o[4] = {0, 0, 0, 0};
#pragma unroll 4
        for (int j = 0; j < 64; j++) {
            ulonglong2 pA = *(const ulonglong2*)&xsD[j][8 * warp];
            ulonglong2 pB = *(const ulonglong2*)&xsD[j][8 * warp + 4];
            ull xv = *(const ull*)&xs[j * 68 + tj2];
            fma2(o[0], pA.x, xv);
            fma2(o[1], pA.y, xv);
            fma2(o[2], pB.x, xv);
            fma2(o[3], pB.y, xv);
        }
        int d = d0 + tj2;
#pragma unroll
        for (int i = 0; i < 4; i++) {
            int grow = row0 + 4 * warp + i;
            float a0, a1;
            upk2(o[i], a0, a1);
            if (residual) {
                float2 xv = *(const float2*)&xs[grow * 68 + tj2];
                a0 += xv.x;
                a1 += xv.y;
            }
            if (d < DM)     OUT[grow * DM + d]     = a0;
            if (d + 1 < DM) OUT[grow * DM + d + 1] = a1;
        }
    }
}

// ---------------------------------------------------------------------------
extern "C" void kernel_launch(void* const* d_in, const int* in_sizes, int n_in,
                              void* d_out, int out_size) {
    const int*   q1     = (const int*)d_in[0];
    const int*   q2     = (const int*)d_in[1];
    const int*   q1_len = (const int*)d_in[2];
    const int*   q2_len = (const int*)d_in[3];
    const int*   q1c    = (const int*)d_in[4];
    const int*   q2c    = (const int*)d_in[5];
    const float* wemb   = (const float*)d_in[6];
    const float* cemb   = (const float*)d_in[7];
    const float* cw3    = (const float*)d_in[8];
    const float* cb3    = (const float*)d_in[9];
    const float* cw4    = (const float*)d_in[10];
    const float* cb4    = (const float*)d_in[11];
    const float* cw5    = (const float*)d_in[12];
    const float* cb5    = (const float*)d_in[13];
    const float* hw_w   = (const float*)d_in[14];
    const float* hw_b   = (const float*)d_in[15];
    const float* attw   = (const float*)d_in[16];
    const float* attb   = (const float*)d_in[17];
    float* out = (float*)d_out;

    float* gx;
    float* gy;
    cudaGetSymbolAddress((void**)&gx, g_x);
    cudaGetSymbolAddress((void**)&gy, g_y);

    precomp_kernel<<<(60000 + 255) / 256, 256>>>(cemb, cw3, cw4, cw5);
    embed_kernel<<<NTOK, 160>>>(q1, q2, q1c, q2c, wemb, cb3, cb4, cb5);
    highway_kernel<<<dim3(8, 64), 256>>>(0, hw_w, hw_b);   // g_x -> g_y
    highway_kernel<<<dim3(8, 64), 256>>>(1, hw_w, hw_b);   // g_y -> g_x
    // attn iter0: g_x -> g_y (att + x) ; iter1: g_y -> out (att)
    sdots_kernel<<<128, 256>>>(gx, attw, 0);
    attn_kernel<<<dim3(2, 128), 256>>>(q1_len, q2_len, attw, attb, 0, 1, gx, gy);
    sdots_kernel<<<128, 256>>>(gy, attw, 1);
    attn_kernel<<<dim3(2, 128), 256>>>(q1_len, q2_len, attw, attb, 1, 0, gy, out);
}

// round 6
// speedup vs baseline: 1.4097x; 1.0713x over previous
#include <cuda_runtime.h>
#include <cstdint>

#define NB 64
#define NL 64
#define NC 16
#define DM 450          // EMB(300) + 3*50
#define NTOK 8192       // 2 * B * L

typedef unsigned long long ull;

__device__ __forceinline__ void upk2(ull v, float& lo, float& hi) {
    asm("mov.b64 {%0, %1}, %2;" : "=f"(lo), "=f"(hi) : "l"(v));
}
__device__ __forceinline__ void fma2(ull& d, ull a, ull b) {
    asm("fma.rn.f32x2 %0, %1, %2, %0;" : "+l"(d) : "l"(a), "l"(b));
}

__device__ float g_x[(size_t)NTOK * DM];
__device__ float g_y[(size_t)NTOK * DM];
__device__ float g_M[60000];
__device__ float g_s1[NTOK];
__device__ float g_s2[NTOK];

// ---------------------------------------------------------------------------
// 1) Precompute char tables: M[k][v][f] = sum_ch cemb[v][ch] * w[f][ch][k]
// ---------------------------------------------------------------------------
__global__ void precomp_kernel(const float* __restrict__ cemb,
                               const float* __restrict__ w3,
                               const float* __restrict__ w4,
                               const float* __restrict__ w5) {
    int idx = blockIdx.x * blockDim.x + threadIdx.x;
    if (idx >= 60000) return;
    const float* W;
    int WD, local;
    if (idx < 15000)      { W = w3; WD = 3; local = idx; }
    else if (idx < 35000) { W = w4; WD = 4; local = idx - 15000; }
    else                  { W = w5; WD = 5; local = idx - 35000; }
    int f  = local % 50;
    int kv = local / 50;
    int v  = kv % 100;
    int k  = kv / 100;
    const float* e  = cemb + v * 64;
    const float* wp = W + (size_t)f * 64 * WD + k;
    float s = 0.f;
#pragma unroll 8
    for (int ch = 0; ch < 64; ch++) s += e[ch] * wp[ch * WD];
    g_M[idx] = s;
}

// ---------------------------------------------------------------------------
// 2) Embedding + char features -> g_x[tok][450]
// ---------------------------------------------------------------------------
__global__ void embed_kernel(const int* __restrict__ q1, const int* __restrict__ q2,
                             const int* __restrict__ q1c, const int* __restrict__ q2c,
                             const float* __restrict__ wemb,
                             const float* __restrict__ b3, const float* __restrict__ b4,
                             const float* __restrict__ b5) {
    int tok = blockIdx.x;
    int r   = tok >> 12;
    int li  = tok & 4095;
    const int* q  = r ? q2 : q1;
    const int* qc = r ? q2c : q1c;
    int tid = threadIdx.x;

    __shared__ int ids[16];
    if (tid < 16) ids[tid] = qc[li * 16 + tid];
    __syncthreads();

    float* xrow = g_x + (size_t)tok * DM;
    const float* we = wemb + (size_t)q[li] * 300;
    for (int i = tid; i < 300; i += blockDim.x) xrow[i] = we[i];

    int f = tid;
    if (f < 150) {
        int fi, base, wd;
        float bias;
        if (f < 50)       { wd = 3; fi = f;       base = 0;     bias = b3[fi]; }
        else if (f < 100) { wd = 4; fi = f - 50;  base = 15000; bias = b4[fi]; }
        else              { wd = 5; fi = f - 100; base = 35000; bias = b5[fi]; }
        float m = 0.f;
        int tout = 16 - wd + 1;
        for (int t = 0; t < tout; t++) {
            float h = bias;
            for (int k = 0; k < wd; k++)
                h += g_M[base + (k * 100 + ids[t + k]) * 50 + fi];
            m = fmaxf(m, h);
        }
        xrow[300 + f] = m;
    }
}

// ---------------------------------------------------------------------------
// 3) Highway: y = x @ W^T + b ; out = sig(y)*relu(y) + (1-sig(y))*x
//    K-PAIR packed f32x2: acc = (even-k sum, odd-k sum); final y = lo+hi.
//    As[m][k], Bs[n][k] natural row-major (stride 36) — zero duplication,
//    zero MOVs. A reads broadcast; B reads lane-consecutive rows (cols
//    strided by 16 per thread) => conflict-free LDS.128.
// ---------------------------------------------------------------------------
#define HBM 128
#define HBN 64
#define HBK 32
#define HKS 36   // row stride (32 k + 4 pad), 16B-aligned rows

__global__ __launch_bounds__(256, 2) void highway_kernel(int dir,
        const float* __restrict__ W, const float* __restrict__ bias) {
    const float* X = dir ? g_y : g_x;
    float* OUT     = dir ? g_x : g_y;
    __shared__ float As[HBM][HKS];
    __shared__ float Bs[HBN][HKS];
    int bm = blockIdx.y * HBM;
    int bn = blockIdx.x * HBN;
    int tid = threadIdx.x;
    int tm = (tid >> 4) * 8;   // 8 rows (broadcast across lanes 0-15)
    int tc = tid & 15;         // cols tc + 16p, p=0..3
    // acc[i][p]: row tm+i, col tc+16p; pair = (even-k, odd-k) partials
    ull acc[8][4] = {};

    for (int k0 = 0; k0 < DM; k0 += HBK) {
        // A tile fill: 128 rows x 16 float2 (k-contiguous)
        for (int idx = tid; idx < HBM * 16; idx += 256) {
            int m = idx >> 4, c = idx & 15;
            int kk = k0 + 2 * c;
            float2 v = make_float2(0.f, 0.f);
            if (kk < DM) v = *(const float2*)&X[(size_t)(bm + m) * DM + kk];
            *(float2*)&As[m][2 * c] = v;
        }
        // B tile fill: 64 rows x 16 float2
        for (int idx = tid; idx < HBN * 16; idx += 256) {
            int n = idx >> 4, c = idx & 15;
            int kk = k0 + 2 * c;
            int gn = bn + n;
            float2 v = make_float2(0.f, 0.f);
            if (gn < DM && kk < DM) v = *(const float2*)&W[(size_t)gn * DM + kk];
            *(float2*)&Bs[n][2 * c] = v;
        }
        __syncthreads();
#pragma unroll
        for (int kq = 0; kq < HBK / 4; kq++) {
            ulonglong2 b0 = *(const ulonglong2*)&Bs[tc][4 * kq];
            ulonglong2 b1 = *(const ulonglong2*)&Bs[tc + 16][4 * kq];
            ulonglong2 b2 = *(const ulonglong2*)&Bs[tc + 32][4 * kq];
            ulonglong2 b3 = *(const ulonglong2*)&Bs[tc + 48][4 * kq];
#pragma unroll
            for (int i = 0; i < 8; i++) {
                ulonglong2 a = *(const ulonglong2*)&As[tm + i][4 * kq];
                fma2(acc[i][0], a.x, b0.x); fma2(acc[i][0], a.y, b0.y);
                fma2(acc[i][1], a.x, b1.x); fma2(acc[i][1], a.y, b1.y);
                fma2(acc[i][2], a.x, b2.x); fma2(acc[i][2], a.y, b2.y);
                fma2(acc[i][3], a.x, b3.x); fma2(acc[i][3], a.y, b3.y);
            }
        }
        __syncthreads();
    }

#pragma unroll
    for (int i = 0; i < 8; i++) {
        int m = bm + tm + i;
#pragma unroll
        for (int p = 0; p < 4; p++) {
            int n = bn + tc + 16 * p;
            if (n < DM) {
                float lo, hi;
                upk2(acc[i][p], lo, hi);
                float yy = lo + hi + bias[n];
                float g  = 1.f / (1.f + __expf(-yy));
                float xv = X[(size_t)m * DM + n];
                OUT[(size_t)m * DM + n] = g * fmaxf(yy, 0.f) + (1.f - g) * xv;
            }
        }
    }
}

// ---------------------------------------------------------------------------
// 4a) s1/s2 dots for one attn iteration: s1 = x.w1, s2 = x.w2, all 64 rows.
// ---------------------------------------------------------------------------
__global__ __launch_bounds__(256) void sdots_kernel(
        const float* __restrict__ Xin_base, const float* __restrict__ attw, int it) {
    int batch = blockIdx.x;
    const float* X  = Xin_base + (size_t)batch * 64 * DM;
    const float* aw = attw + it * (3 * DM);
    int tid = threadIdx.x;
    int warp = tid >> 5, lane = tid & 31;

    for (int dot = warp; dot < 128; dot += 8) {
        int row = dot & 63;
        const float* wv = (dot < 64) ? (aw + DM) : aw;
        const float* xv = X + row * DM;
        float a = 0.f;
        for (int d = lane * 2; d < DM; d += 64) {
            float2 x2 = *(const float2*)&xv[d];
            float2 w2 = *(const float2*)&wv[d];
            a += x2.x * w2.x + x2.y * w2.y;
        }
#pragma unroll
        for (int off = 16; off > 0; off >>= 1)
            a += __shfl_down_sync(0xffffffffu, a, off);
        if (lane == 0) {
            if (dot < 64) g_s2[batch * 64 + row] = a;
            else          g_s1[batch * 64 + row] = a;
        }
    }
}

// ---------------------------------------------------------------------------
// 4b) Self-attention: grid (2, 128), block = (batch, 32-row group), 256 thr.
// ---------------------------------------------------------------------------
__global__ __launch_bounds__(256) void attn_kernel(
        const int* __restrict__ q1_len, const int* __restrict__ q2_len,
        const float* __restrict__ attw, const float* __restrict__ attb,
        int it, int residual,
        const float* __restrict__ Xin_base, float* __restrict__ Xout_base) {
    int batch = blockIdx.y;
    int row0  = blockIdx.x * 32;
    int r = batch >> 6, b = batch & 63;
    int len = (r ? q2_len : q1_len)[b];
    const float* aw = attw + it * (3 * DM);
    float ab = attb[it];
    const float* X = Xin_base + (size_t)batch * 64 * DM;
    float* OUT     = Xout_base + (size_t)batch * 64 * DM;

    __shared__ float xw[64][68];
    __shared__ float xsD[64][68];
    __shared__ float s1s[32], s2s[64];

    int tid  = threadIdx.x;
    int warp = tid >> 5, lane = tid & 31;
    int tj2  = lane * 2;

    if (tid < 64)      s2s[tid] = g_s2[batch * 64 + tid];
    else if (tid < 96) s1s[tid - 64] = g_s1[batch * 64 + row0 + (tid - 64)] + ab;

    ull acc[4] = {0, 0, 0, 0};

    for (int d0 = 0; d0 < DM; d0 += 64) {
        int dn = DM - d0; if (dn > 64) dn = 64;
        __syncthreads();
        for (int idx = tid; idx < 64 * 64; idx += 256) {
            int j = idx >> 6, d = idx & 63;
            float v = 0.f;
            if (d < dn) v = X[j * DM + d0 + d] * aw[2 * DM + d0 + d];
            xw[d][j] = v;
        }
        for (int idx = tid; idx < 32 * 64; idx += 256) {
            int rr = idx >> 6, d = idx & 63;
            float v = (d < dn) ? X[(row0 + rr) * DM + d0 + d] : 0.f;
            *(float2*)&xsD[d][2 * rr] = make_float2(v, v);
        }
        __syncthreads();
#pragma unroll 4
        for (int d = 0; d < 64; d++) {
            ulonglong2 aA = *(const ulonglong2*)&xsD[d][8 * warp];
            ulonglong2 aB = *(const ulonglong2*)&xsD[d][8 * warp + 4];
            ull bw = *(const ull*)&xw[d][tj2];
            fma2(acc[0], aA.x, bw);
            fma2(acc[1], aA.y, bw);
            fma2(acc[2], aB.x, bw);
            fma2(acc[3], aB.y, bw);
        }
    }
    __syncthreads();

    {
        float2 s2p = *(const float2*)&s2s[tj2];
#pragma unroll
        for (int i = 0; i < 4; i++) {
            int lr = 4 * warp + i;
            float base = s1s[lr];
            float v0, v1;
            upk2(acc[i], v0, v1);
            v0 += base + s2p.x;
            v1 += base + s2p.y;
            float l0 = (tj2     < len) ? v0 : -1e-9f;
            float l1 = (tj2 + 1 < len) ? v1 : -1e-9f;
            float mx = fmaxf(l0, l1);
#pragma unroll
            for (int off = 16; off > 0; off >>= 1)
                mx = fmaxf(mx, __shfl_xor_sync(0xffffffffu, mx, off));
            float e0 = __expf(l0 - mx), e1 = __expf(l1 - mx);
            float s = e0 + e1;
#pragma unroll
            for (int off = 16; off > 0; off >>= 1)
                s += __shfl_xor_sync(0xffffffffu, s, off);
            float inv = 1.f / s;
            *(float2*)&xsD[tj2][2 * lr]     = make_float2(e0 * inv, e0 * inv);
            *(float2*)&xsD[tj2 + 1][2 * lr] = make_float2(e1 * inv, e1 * inv);
        }
    }

    float* xs = &xw[0][0];
    for (int d0 = 0; d0 < DM; d0 += 64) {
        int dn = DM - d0; if (dn > 64) dn = 64;
        __syncthreads();
        for (int idx = tid; idx < 64 * 32; idx += 256) {
            int j = idx >> 5, dp = idx & 31;
            float2 v = make_float2(0.f, 0.f);
            if (2 * dp < dn) v = *(const float2*)&X[j * DM + d0 + 2 * dp];
            *(float2*)&xs[j * 68 + 2 * dp] = v;
        }
        __syncthreads();
        ull o[4] = {0, 0, 0, 0};
#pragma unroll 4
        for (int j = 0; j < 64; j++) {
            ulonglong2 pA = *(const ulonglong2*)&xsD[j][8 * warp];
            ulonglong2 pB = *(const ulonglong2*)&xsD[j][8 * warp + 4];
            ull xv = *(const ull*)&xs[j * 68 + tj2];
            fma2(o[0], pA.x, xv);
            fma2(o[1], pA.y, xv);
            fma2(o[2], pB.x, xv);
            fma2(o[3], pB.y, xv);
        }
        int d = d0 + tj2;
#pragma unroll
        for (int i = 0; i < 4; i++) {
            int grow = row0 + 4 * warp + i;
            float a0, a1;
            upk2(o[i], a0, a1);
            if (residual) {
                float2 xv = *(const float2*)&xs[grow * 68 + tj2];
                a0 += xv.x;
                a1 += xv.y;
            }
            if (d < DM)     OUT[grow * DM + d]     = a0;
            if (d + 1 < DM) OUT[grow * DM + d + 1] = a1;
        }
    }
}

// ---------------------------------------------------------------------------
extern "C" void kernel_launch(void* const* d_in, const int* in_sizes, int n_in,
                              void* d_out, int out_size) {
    const int*   q1     = (const int*)d_in[0];
    const int*   q2     = (const int*)d_in[1];
    const int*   q1_len = (const int*)d_in[2];
    const int*   q2_len = (const int*)d_in[3];
    const int*   q1c    = (const int*)d_in[4];
    const int*   q2c    = (const int*)d_in[5];
    const float* wemb   = (const float*)d_in[6];
    const float* cemb   = (const float*)d_in[7];
    const float* cw3    = (const float*)d_in[8];
    const float* cb3    = (const float*)d_in[9];
    const float* cw4    = (const float*)d_in[10];
    const float* cb4    = (const float*)d_in[11];
    const float* cw5    = (const float*)d_in[12];
    const float* cb5    = (const float*)d_in[13];
    const float* hw_w   = (const float*)d_in[14];
    const float* hw_b   = (const float*)d_in[15];
    const float* attw   = (const float*)d_in[16];
    const float* attb   = (const float*)d_in[17];
    float* out = (float*)d_out;

    float* gx;
    float* gy;
    cudaGetSymbolAddress((void**)&gx, g_x);
    cudaGetSymbolAddress((void**)&gy, g_y);

    precomp_kernel<<<(60000 + 255) / 256, 256>>>(cemb, cw3, cw4, cw5);
    embed_kernel<<<NTOK, 160>>>(q1, q2, q1c, q2c, wemb, cb3, cb4, cb5);
    highway_kernel<<<dim3(8, 64), 256>>>(0, hw_w, hw_b);   // g_x -> g_y
    highway_kernel<<<dim3(8, 64), 256>>>(1, hw_w, hw_b);   // g_y -> g_x
    sdots_kernel<<<128, 256>>>(gx, attw, 0);
    attn_kernel<<<dim3(2, 128), 256>>>(q1_len, q2_len, attw, attb, 0, 1, gx, gy);
    sdots_kernel<<<128, 256>>>(gy, attw, 1);
    attn_kernel<<<dim3(2, 128), 256>>>(q1_len, q2_len, attw, attb, 1, 0, gy, out);
}